// round 6
// baseline (speedup 1.0000x reference)
#include <cuda_runtime.h>

// Fixed shapes for CIFAR10Net_86096914416128
#define TT    16
#define NB    32
#define CIN   3
#define HH    32
#define WWID  32
#define COUT  128
#define KW27  27

// x tile (u64 units): per t, 9 rows (cin*3+kh) x 34 logical cols, padded
#define ROWS9   9
#define RSTRIDE 38                  // 34 + 2x2 gaps -> 304B rows, 16B aligned
#define TSTRIDE (ROWS9 * RSTRIDE)   // 342 u64 per time step
#define TCHUNK  8
#define NPAIRS_T (ROWS9 * 34)       // 306 logical pairs per t

typedef unsigned long long u64;

__device__ float g_w[COUT * KW27];

// ---------- packed f32x2 helpers ----------
__device__ __forceinline__ u64 pack2(float a, float b) {
    u64 r; asm("mov.b64 %0,{%1,%2};" : "=l"(r) : "f"(a), "f"(b)); return r;
}
__device__ __forceinline__ void unpack2(u64 v, float& a, float& b) {
    asm("mov.b64 {%0,%1},%2;" : "=f"(a), "=f"(b) : "l"(v));
}
__device__ __forceinline__ u64 ffma2(u64 a, u64 b, u64 c) {
    asm("fma.rn.f32x2 %0,%1,%2,%0;" : "+l"(c) : "l"(a), "l"(b)); return c;
}
__device__ __forceinline__ u64 fadd2(u64 a, u64 b) {
    u64 r; asm("add.rn.f32x2 %0,%1,%2;" : "=l"(r) : "l"(a), "l"(b)); return r;
}
__device__ __forceinline__ u64 fmul2(u64 a, u64 b) {
    u64 r; asm("mul.rn.f32x2 %0,%1,%2;" : "=l"(r) : "l"(a), "l"(b)); return r;
}

// conflict-free column map: 16B gap every 16 cols (chunk starts stay even)
__device__ __forceinline__ int colmap(int c) { return c + 2 * (c >> 4); }

// ---------- weight prep: clip + fp32 weight-standardization (matches ref) ----------
__global__ void prep_kernel(const float* __restrict__ w,
                            const float* __restrict__ nw,
                            const float* __restrict__ nb) {
    int c = threadIdx.x;
    if (c >= COUT) return;
    float v[KW27];
    float s = 0.0f;
#pragma unroll
    for (int i = 0; i < KW27; i++) {
        float t = w[c * KW27 + i];
        t = fminf(4.0f, fmaxf(-4.0f, t));
        v[i] = t;
        s = __fadd_rn(s, t);
    }
    float mean = __fdiv_rn(s, 27.0f);
    float ss = 0.0f;
#pragma unroll
    for (int i = 0; i < KW27; i++) {
        float d = __fsub_rn(v[i], mean);
        ss = __fadd_rn(ss, __fmul_rn(d, d));
    }
    float var   = __fdiv_rn(ss, 26.0f);
    float denom = __fsqrt_rn(__fadd_rn(var, 1e-5f));
    float nwc = nw[c];
    float nbc = nb[c];
#pragma unroll
    for (int i = 0; i < KW27; i++) {
        float std = __fdiv_rn(__fsub_rn(v[i], mean), denom);
        g_w[c * KW27 + i] = __fadd_rn(__fmul_rn(std, nwc), nbc);
    }
}

// ---------- fused conv3x3 + LIF scan ----------
// Lanes = row pair (dense). Each thread: 2 channels x 2 rows x 4 cols = 16 out.
// Grid: 1024 = b(32) * cgroup(2, 64ch) * row_pair(16). Block: 256 = cp(32)*seg(8).
// Weights live in smem, reloaded per cin-phase (18 live regs, not 108).
__global__ void __launch_bounds__(256, 2)
snn_kernel(const float* __restrict__ x,
           const float* __restrict__ thr,
           float* __restrict__ out) {
    __shared__ __align__(16) u64 xs[TCHUNK * TSTRIDE];   // 21888 B
    __shared__ __align__(16) u64 wsm[64 * KW27];         // 13824 B (dup pairs)

    const int tid = threadIdx.x;
    const int bid = blockIdx.x;
    const int bb  = bid >> 5;          // batch
    const int cg  = (bid >> 4) & 1;    // 64-channel group
    const int rs  = bid & 15;          // row pair
    const int r0  = rs * 2;

    const int cp  = tid >> 3;          // channel pair 0..31
    const int seg = tid & 7;
    const int w0  = seg * 4;
    const int cA  = cp * 2;            // local channels in group
    const int c0  = cg * 64 + cA;      // global channel A (B = c0+1)

    // stage standardized weights as duplicated f32x2 pairs
    for (int idx = tid; idx < 64 * KW27; idx += 256) {
        float wv = g_w[(cg * 64 + idx / KW27) * KW27 + (idx % KW27)];
        wsm[idx] = pack2(wv, wv);
    }

    const float thA = thr[c0];
    const float thB = thr[c0 + 1];
    const float CSG = 1.0f - (float)(1.0 / 3.5);
    const u64 C2 = pack2(CSG, CSG);

    const int HW = HH * WWID;

    // LIF state: lanes = (row r0, row r0+1); 4 cols x 2 channels
    u64 uA[4]  = {0,0,0,0}, sgA[4] = {0,0,0,0};
    u64 uB[4]  = {0,0,0,0}, sgB[4] = {0,0,0,0};

    const int oo0 = colmap(w0);
    const int oo1 = colmap(w0 + 2);
    const int oo2 = colmap(w0 + 4);
    const u64* wpA = wsm + cA * KW27;
    const u64* wpB = wsm + (cA + 1) * KW27;

    float* ob = out + ((size_t)bb * COUT + c0) * HW + (size_t)r0 * WWID + w0;
    const size_t ostride = (size_t)NB * COUT * HW;

    for (int h = 0; h < TT / TCHUNK; h++) {
        __syncthreads();   // previous phase readers done (also fences wsm writes)
        // ---- stage TCHUNK timesteps as vertical row pairs ----
        for (int idx = tid; idx < TCHUNK * NPAIRS_T; idx += 256) {
            int t   = idx / NPAIRS_T;
            int rem = idx - t * NPAIRS_T;
            int row = rem / 34;            // cin*3 + jj
            int col = rem - row * 34;
            int cin = row / 3;
            int jj  = row - cin * 3;
            int gw  = col - 1;
            float va = 0.0f, vb = 0.0f;
            if (gw >= 0 && gw < WWID) {
                int ra = r0 - 1 + jj;      // [-1, 31]
                int rb = r0 + jj;          // [0, 32]
                const float* p = x + ((size_t)((h * TCHUNK + t) * NB + bb) * CIN + cin) * HW + gw;
                if (ra >= 0 && ra < HH) va = p[ra * WWID];
                if (rb < HH)            vb = p[rb * WWID];
            }
            xs[t * TSTRIDE + row * RSTRIDE + colmap(col)] = pack2(va, vb);
        }
        __syncthreads();

#pragma unroll 1
        for (int t = 0; t < TCHUNK; t++) {
            const u64* tb = xs + t * TSTRIDE;

            u64 accA[4] = {0,0,0,0};
            u64 accB[4] = {0,0,0,0};
#pragma unroll
            for (int cin = 0; cin < 3; cin++) {
                // weights for this cin: 9 per channel
                u64 wa[9], wb[9];
#pragma unroll
                for (int i = 0; i < 9; i++) {
                    wa[i] = wpA[cin * 9 + i];
                    wb[i] = wpB[cin * 9 + i];
                }
#pragma unroll
                for (int kh = 0; kh < 3; kh++) {
                    const u64* rowp = tb + (cin * 3 + kh) * RSTRIDE;
                    ulonglong2 p0 = *reinterpret_cast<const ulonglong2*>(rowp + oo0);
                    ulonglong2 p1 = *reinterpret_cast<const ulonglong2*>(rowp + oo1);
                    ulonglong2 p2 = *reinterpret_cast<const ulonglong2*>(rowp + oo2);
                    u64 xr[6] = {p0.x, p0.y, p1.x, p1.y, p2.x, p2.y};
#pragma unroll
                    for (int kw = 0; kw < 3; kw++) {
                        const u64 wva = wa[kh * 3 + kw];
                        const u64 wvb = wb[kh * 3 + kw];
#pragma unroll
                        for (int ww = 0; ww < 4; ww++) {
                            accA[ww] = ffma2(wva, xr[ww + kw], accA[ww]);
                            accB[ww] = ffma2(wvb, xr[ww + kw], accB[ww]);
                        }
                    }
                }
            }

            // LIF update + spike/reset; lanes are rows, scalar thr per channel
            float a0[4], a1[4], b0[4], b1[4];
#pragma unroll
            for (int k = 0; k < 4; k++) {
                u64 s  = fmul2(fadd2(sgA[k], accA[k]), C2);
                u64 uu = fadd2(uA[k], s);
                float ux, uy, sx, sy;
                unpack2(uu, ux, uy);
                unpack2(s,  sx, sy);
                a0[k] = (ux >= thA) ? 1.0f : 0.0f;
                a1[k] = (uy >= thA) ? 1.0f : 0.0f;
                if (ux >= thA) { ux = 0.0f; sx = 0.0f; }
                if (uy >= thA) { uy = 0.0f; sy = 0.0f; }
                uA[k]  = pack2(ux, uy);
                sgA[k] = pack2(sx, sy);

                s  = fmul2(fadd2(sgB[k], accB[k]), C2);
                uu = fadd2(uB[k], s);
                unpack2(uu, ux, uy);
                unpack2(s,  sx, sy);
                b0[k] = (ux >= thB) ? 1.0f : 0.0f;
                b1[k] = (uy >= thB) ? 1.0f : 0.0f;
                if (ux >= thB) { ux = 0.0f; sx = 0.0f; }
                if (uy >= thB) { uy = 0.0f; sy = 0.0f; }
                uB[k]  = pack2(ux, uy);
                sgB[k] = pack2(sx, sy);
            }
            float* op = ob + (size_t)(h * TCHUNK + t) * ostride;
            *reinterpret_cast<float4*>(op)             = make_float4(a0[0], a0[1], a0[2], a0[3]);
            *reinterpret_cast<float4*>(op + WWID)      = make_float4(a1[0], a1[1], a1[2], a1[3]);
            *reinterpret_cast<float4*>(op + HW)        = make_float4(b0[0], b0[1], b0[2], b0[3]);
            *reinterpret_cast<float4*>(op + HW + WWID) = make_float4(b1[0], b1[1], b1[2], b1[3]);
        }
    }
}

extern "C" void kernel_launch(void* const* d_in, const int* in_sizes, int n_in,
                              void* d_out, int out_size) {
    const float* x  = (const float*)d_in[0];   // [16,32,3,32,32]
    const float* w  = (const float*)d_in[1];   // [128,3,3,3]
    const float* nw = (const float*)d_in[2];   // [128]
    const float* nb = (const float*)d_in[3];   // [128]
    const float* th = (const float*)d_in[4];   // [128]
    float* out = (float*)d_out;                // [16,32,128,32,32]

    prep_kernel<<<1, 128>>>(w, nw, nb);
    snn_kernel<<<1024, 256>>>(x, th, out);
}

// round 7
// speedup vs baseline: 1.4287x; 1.4287x over previous
#include <cuda_runtime.h>

// Fixed shapes for CIFAR10Net_86096914416128
#define TT    16
#define NB    32
#define CIN   3
#define HH    32
#define WWID  32
#define COUT  128
#define KW27  27

// x tile (u64 units): per t, 15 pair-rows (cin*5 + j) x 34 logical cols
#define PROWS   5                    // pair-rows per cin (j=0..4, start r0-1+j)
#define NROWS   (CIN * PROWS)        // 15
#define RSTRIDE 38                   // 34 + 2x2 gaps -> 304B rows, 16B aligned
#define TSTRIDE (NROWS * RSTRIDE)    // 570 u64 per time step
#define TCHUNK  8
#define NPAIRS_T (NROWS * 34)        // 510 logical pairs per t

typedef unsigned long long u64;

__device__ float g_w[COUT * KW27];

// ---------- packed f32x2 helpers ----------
__device__ __forceinline__ u64 pack2(float a, float b) {
    u64 r; asm("mov.b64 %0,{%1,%2};" : "=l"(r) : "f"(a), "f"(b)); return r;
}
__device__ __forceinline__ void unpack2(u64 v, float& a, float& b) {
    asm("mov.b64 {%0,%1},%2;" : "=f"(a), "=f"(b) : "l"(v));
}
__device__ __forceinline__ u64 ffma2(u64 a, u64 b, u64 c) {
    asm("fma.rn.f32x2 %0,%1,%2,%0;" : "+l"(c) : "l"(a), "l"(b)); return c;
}
__device__ __forceinline__ u64 fadd2(u64 a, u64 b) {
    u64 r; asm("add.rn.f32x2 %0,%1,%2;" : "=l"(r) : "l"(a), "l"(b)); return r;
}
__device__ __forceinline__ u64 fmul2(u64 a, u64 b) {
    u64 r; asm("mul.rn.f32x2 %0,%1,%2;" : "=l"(r) : "l"(a), "l"(b)); return r;
}

// conflict-free column map: 16B gap every 16 cols (chunk starts stay even)
__device__ __forceinline__ int colmap(int c) { return c + 2 * (c >> 4); }

// ---------- weight prep: clip + fp32 weight-standardization (matches ref) ----------
__global__ void prep_kernel(const float* __restrict__ w,
                            const float* __restrict__ nw,
                            const float* __restrict__ nb) {
    int c = threadIdx.x;
    if (c >= COUT) return;
    float v[KW27];
    float s = 0.0f;
#pragma unroll
    for (int i = 0; i < KW27; i++) {
        float t = w[c * KW27 + i];
        t = fminf(4.0f, fmaxf(-4.0f, t));
        v[i] = t;
        s = __fadd_rn(s, t);
    }
    float mean = __fdiv_rn(s, 27.0f);
    float ss = 0.0f;
#pragma unroll
    for (int i = 0; i < KW27; i++) {
        float d = __fsub_rn(v[i], mean);
        ss = __fadd_rn(ss, __fmul_rn(d, d));
    }
    float var   = __fdiv_rn(ss, 26.0f);
    float denom = __fsqrt_rn(__fadd_rn(var, 1e-5f));
    float nwc = nw[c];
    float nbc = nb[c];
#pragma unroll
    for (int i = 0; i < KW27; i++) {
        float std = __fdiv_rn(__fsub_rn(v[i], mean), denom);
        g_w[c * KW27 + i] = __fadd_rn(__fmul_rn(std, nwc), nbc);
    }
}

// ---------- fused conv3x3 + LIF scan; 4 output rows per thread ----------
// Grid: 1024 = b(32) * cgroup(4, 32ch) * rowquad(8). Block: 256 = ch(32)*seg(8).
// Thread: 1 channel, 4 rows (two f32x2 pair-accs P,Q), 4 cols = 16 outputs.
__global__ void __launch_bounds__(256, 2)
snn_kernel(const float* __restrict__ x,
           const float* __restrict__ thr,
           float* __restrict__ out) {
    __shared__ __align__(16) u64 xs[TCHUNK * TSTRIDE];   // 4560 u64 = 36480 B

    const int tid = threadIdx.x;
    const int bid = blockIdx.x;
    const int bb  = bid >> 5;          // batch
    const int cg  = (bid >> 3) & 3;    // 32-channel group
    const int rq  = bid & 7;           // row quad
    const int r0  = rq * 4;

    const int cl  = tid >> 3;          // channel in group
    const int seg = tid & 7;
    const int w0  = seg * 4;
    const int c   = cg * 32 + cl;

    // 27 weights duplicated into both f32x2 lanes (registers)
    u64 wp[KW27];
#pragma unroll
    for (int i = 0; i < KW27; i++) {
        float wv = g_w[c * KW27 + i];
        wp[i] = pack2(wv, wv);
    }
    const float th = thr[c];
    const float CSG = 1.0f - (float)(1.0 / 3.5);
    const u64 C2 = pack2(CSG, CSG);

    const int HW = HH * WWID;

    // LIF state: P = rows (r0, r0+1), Q = rows (r0+2, r0+3); 4 cols each
    u64 uP[4]  = {0,0,0,0}, sgP[4] = {0,0,0,0};
    u64 uQ[4]  = {0,0,0,0}, sgQ[4] = {0,0,0,0};

    const int oo0 = colmap(w0);
    const int oo1 = colmap(w0 + 2);
    const int oo2 = colmap(w0 + 4);

    float* ob = out + ((size_t)bb * COUT + c) * HW + (size_t)r0 * WWID + w0;
    const size_t ostride = (size_t)NB * COUT * HW;

    for (int h = 0; h < TT / TCHUNK; h++) {
        __syncthreads();   // previous phase readers done
        // ---- stage TCHUNK timesteps: pair-row j covers global rows (r0-1+j, r0+j) ----
        for (int idx = tid; idx < TCHUNK * NPAIRS_T; idx += 256) {
            int t   = idx / NPAIRS_T;
            int rem = idx - t * NPAIRS_T;
            int row = rem / 34;            // cin*5 + j
            int col = rem - row * 34;
            int cin = row / PROWS;
            int j   = row - cin * PROWS;
            int gw  = col - 1;
            float va = 0.0f, vb = 0.0f;
            if (gw >= 0 && gw < WWID) {
                int ra = r0 - 1 + j;       // [-1, 31]
                int rb = r0 + j;           // [0, 32]
                const float* p = x + ((size_t)((h * TCHUNK + t) * NB + bb) * CIN + cin) * HW + gw;
                if (ra >= 0 && ra < HH) va = p[ra * WWID];
                if (rb < HH)            vb = p[rb * WWID];
            }
            xs[t * TSTRIDE + row * RSTRIDE + colmap(col)] = pack2(va, vb);
        }
        __syncthreads();

#pragma unroll 1
        for (int t = 0; t < TCHUNK; t++) {
            const u64* tb = xs + t * TSTRIDE;

            u64 accP[4] = {0,0,0,0};
            u64 accQ[4] = {0,0,0,0};
#pragma unroll
            for (int cin = 0; cin < 3; cin++) {
#pragma unroll
                for (int j = 0; j < PROWS; j++) {
                    const u64* rowp = tb + (cin * PROWS + j) * RSTRIDE;
                    ulonglong2 p0 = *reinterpret_cast<const ulonglong2*>(rowp + oo0);
                    ulonglong2 p1 = *reinterpret_cast<const ulonglong2*>(rowp + oo1);
                    ulonglong2 p2 = *reinterpret_cast<const ulonglong2*>(rowp + oo2);
                    u64 xr[6] = {p0.x, p0.y, p1.x, p1.y, p2.x, p2.y};
                    if (j < 3) {                 // P: kh = j
                        const int wb = (cin * 3 + j) * 3;
#pragma unroll
                        for (int kw = 0; kw < 3; kw++) {
                            const u64 wv = wp[wb + kw];
#pragma unroll
                            for (int ww = 0; ww < 4; ww++)
                                accP[ww] = ffma2(wv, xr[ww + kw], accP[ww]);
                        }
                    }
                    if (j >= 2) {                // Q: kh = j - 2
                        const int wb = (cin * 3 + (j - 2)) * 3;
#pragma unroll
                        for (int kw = 0; kw < 3; kw++) {
                            const u64 wv = wp[wb + kw];
#pragma unroll
                            for (int ww = 0; ww < 4; ww++)
                                accQ[ww] = ffma2(wv, xr[ww + kw], accQ[ww]);
                        }
                    }
                }
            }

            // LIF update + spike/reset for both pair sets
            float p0v[4], p1v[4], q0v[4], q1v[4];
#pragma unroll
            for (int k = 0; k < 4; k++) {
                u64 s  = fmul2(fadd2(sgP[k], accP[k]), C2);   // sg=(sg+I)*(1-tg)
                u64 uu = fadd2(uP[k], s);                     // u = u_last + sg
                float ux, uy, sx, sy;
                unpack2(uu, ux, uy);
                unpack2(s,  sx, sy);
                p0v[k] = (ux >= th) ? 1.0f : 0.0f;
                p1v[k] = (uy >= th) ? 1.0f : 0.0f;
                if (ux >= th) { ux = 0.0f; sx = 0.0f; }
                if (uy >= th) { uy = 0.0f; sy = 0.0f; }
                uP[k]  = pack2(ux, uy);
                sgP[k] = pack2(sx, sy);

                s  = fmul2(fadd2(sgQ[k], accQ[k]), C2);
                uu = fadd2(uQ[k], s);
                unpack2(uu, ux, uy);
                unpack2(s,  sx, sy);
                q0v[k] = (ux >= th) ? 1.0f : 0.0f;
                q1v[k] = (uy >= th) ? 1.0f : 0.0f;
                if (ux >= th) { ux = 0.0f; sx = 0.0f; }
                if (uy >= th) { uy = 0.0f; sy = 0.0f; }
                uQ[k]  = pack2(ux, uy);
                sgQ[k] = pack2(sx, sy);
            }
            float* op = ob + (size_t)(h * TCHUNK + t) * ostride;
            *reinterpret_cast<float4*>(op)            = make_float4(p0v[0], p0v[1], p0v[2], p0v[3]);
            *reinterpret_cast<float4*>(op + WWID)     = make_float4(p1v[0], p1v[1], p1v[2], p1v[3]);
            *reinterpret_cast<float4*>(op + 2 * WWID) = make_float4(q0v[0], q0v[1], q0v[2], q0v[3]);
            *reinterpret_cast<float4*>(op + 3 * WWID) = make_float4(q1v[0], q1v[1], q1v[2], q1v[3]);
        }
    }
}

extern "C" void kernel_launch(void* const* d_in, const int* in_sizes, int n_in,
                              void* d_out, int out_size) {
    const float* x  = (const float*)d_in[0];   // [16,32,3,32,32]
    const float* w  = (const float*)d_in[1];   // [128,3,3,3]
    const float* nw = (const float*)d_in[2];   // [128]
    const float* nb = (const float*)d_in[3];   // [128]
    const float* th = (const float*)d_in[4];   // [128]
    float* out = (float*)d_out;                // [16,32,128,32,32]

    prep_kernel<<<1, 128>>>(w, nw, nb);
    snn_kernel<<<1024, 256>>>(x, th, out);
}